// round 16
// baseline (speedup 1.0000x reference)
#include <cuda_runtime.h>
#include <cuda_fp16.h>
#include <math.h>
#include <stdint.h>

// Problem dims
#define Bv    2
#define NQv   1024
#define NKVv  2048
#define Dv    1024
#define Hv    16
#define DHv   64
#define Ev    8
#define FFv   4096
#define TQ    (Bv*NQv)
#define TKV   (Bv*NKVv)
#define MAXTOK 2048

// ---------------- scratch ----------------
__device__ float  g_x[TQ*Dv];
__device__ float  g_ln1[TQ*Dv];
__device__ float  g_lnkv[TKV*Dv];
__device__ float  g_qp[TQ*Dv];
__device__ float  g_kvp[TKV*2048];
__device__ float  g_ao[TQ*Dv];
__device__ __half g_hh[(size_t)TQ*2*FFv];    // MoE hidden, fp16
__device__ float  g_eo[(size_t)TQ*2*Dv];
__device__ float  g_probs[TQ*2];
__device__ int    g_counts[Ev];
__device__ int    g_elist[Ev*MAXTOK];

// ---------------- layernorm ----------------
__global__ void ln_k(const float* __restrict__ x, float* __restrict__ y,
                     const float* __restrict__ g, const float* __restrict__ b) {
    long row = blockIdx.x;
    const float* xr = x + row * 1024;
    float* yr = y + row * 1024;
    __shared__ float sm[1024];
    __shared__ float red[256];
    int tid = threadIdx.x;
    float s = 0.f;
    #pragma unroll
    for (int i = 0; i < 4; i++) { float v = xr[tid + (i<<8)]; sm[tid + (i<<8)] = v; s += v; }
    red[tid] = s; __syncthreads();
    for (int st = 128; st > 0; st >>= 1) { if (tid < st) red[tid] += red[tid + st]; __syncthreads(); }
    float mean = red[0] * (1.0f/1024.0f); __syncthreads();
    float s2 = 0.f;
    #pragma unroll
    for (int i = 0; i < 4; i++) { float d = sm[tid + (i<<8)] - mean; s2 += d*d; }
    red[tid] = s2; __syncthreads();
    for (int st = 128; st > 0; st >>= 1) { if (tid < st) red[tid] += red[tid + st]; __syncthreads(); }
    float var = red[0] * (1.0f/1024.0f);
    float rstd = rsqrtf(var + 1e-5f);
    #pragma unroll
    for (int i = 0; i < 4; i++) { int c = tid + (i<<8); yr[c] = (sm[c]-mean)*rstd*g[c] + b[c]; }
}

// ---------------- fp16 pack/split helpers ----------------
__device__ __forceinline__ unsigned hpack2(float x0, float x1) {
    __half2 h = __floats2half2_rn(x0, x1);
    return *(unsigned*)&h;
}
__device__ __forceinline__ uint2 hsplit2(float x0, float x1) {
    unsigned h = hpack2(x0, x1);
    __half2 hh = *(__half2*)&h;
    float r0 = x0 - __low2float(hh);
    float r1 = x1 - __high2float(hh);
    return make_uint2(h, hpack2(r0, r1));
}
__device__ __forceinline__ void hsplit4(float4 v, unsigned* h2, unsigned* l2) {
    uint2 p0 = hsplit2(v.x, v.y);
    uint2 p1 = hsplit2(v.z, v.w);
    h2[0] = p0.x; h2[1] = p1.x;
    l2[0] = p0.y; l2[1] = p1.y;
}
__device__ __forceinline__ void hpack4(float4 v, unsigned* h2) {
    h2[0] = hpack2(v.x, v.y);
    h2[1] = hpack2(v.z, v.w);
}

__device__ __forceinline__ void mma16(float* c, const unsigned* a, const unsigned* b) {
    asm volatile("mma.sync.aligned.m16n8k16.row.col.f32.f16.f16.f32 "
        "{%0,%1,%2,%3},{%4,%5,%6,%7},{%8,%9},{%0,%1,%2,%3};"
        : "+f"(c[0]), "+f"(c[1]), "+f"(c[2]), "+f"(c[3])
        : "r"(a[0]), "r"(a[1]), "r"(a[2]), "r"(a[3]), "r"(b[0]), "r"(b[1]));
}

__device__ __forceinline__ void ldsm4(const unsigned* p, unsigned* r) {
    unsigned addr = (unsigned)__cvta_generic_to_shared(p);
    asm volatile("ldmatrix.sync.aligned.m8n8.x4.shared.b16 {%0,%1,%2,%3}, [%4];"
        : "=r"(r[0]), "=r"(r[1]), "=r"(r[2]), "=r"(r[3]) : "r"(addr));
}

// Unified GEMM smem layout: [row][kpair 0..15] stride 20 words
#define ASTR 20
// 2-term buffers (projections): A hi+lo, B hi
#define BUFW 6400
#define OFF_AL 2560
#define OFF_BH 5120
#define DSMEM_BYTES (2*BUFW*4)
// 1-term buffers (MoE): A hi, B hi
#define MBUFW 3840
#define MOFF_BH 2560
#define MDSMEM_BYTES (2*MBUFW*4)

// ---- staging coordinate maps (conflict-free STS.128) ----
// A: warp covers 16 rows; quarter holds rows {r,r+1,r+4,r+5} x kh(0/1)
__device__ __forceinline__ void a_stage_coords(int tid, int& rowA, int& khA, int& aoffs) {
    int sl = tid & 31, sw = tid >> 5;
    int Qq = sl >> 3, jj = sl & 7;
    int rr = jj >> 1;  khA = jj & 1;
    rowA = sw*16 + (Qq&1)*2 + ((Qq>>1)&1)*8 + (rr&1) + ((rr>>1)&1)*4;
    aoffs = rowA*ASTR + khA*8;
}
// B: warp covers 8 rows; quarter holds rows {r,r+4} x kq(0..3)
__device__ __forceinline__ void b_stage_coords(int tid, int& rowB, int& kqB, int& boffs) {
    int sl = tid & 31, sw = tid >> 5;
    int Qq = sl >> 3, jj = sl & 7;
    kqB = jj & 3;
    rowB = sw*8 + Qq + ((jj>>2)&1)*4;
    boffs = rowB*ASTR + kqB*4;
}

// stage one A row-half (16 floats -> hi+lo, 4x STS.128)
__device__ __forceinline__ void stage_A2(unsigned* AsH, unsigned* AsL, int aoffs, const float4* a4) {
    unsigned h[8], lo[8];
    hsplit4(a4[0], h,   lo);
    hsplit4(a4[1], h+2, lo+2);
    hsplit4(a4[2], h+4, lo+4);
    hsplit4(a4[3], h+6, lo+6);
    *(uint4*)&AsH[aoffs]   = *(uint4*)h;
    *(uint4*)&AsH[aoffs+4] = *(uint4*)(h+4);
    *(uint4*)&AsL[aoffs]   = *(uint4*)lo;
    *(uint4*)&AsL[aoffs+4] = *(uint4*)(lo+4);
}
// stage one A row-half hi-only (2x STS.128)
__device__ __forceinline__ void stage_A1(unsigned* AsH, int aoffs, const float4* a4) {
    unsigned h[8];
    hpack4(a4[0], h);
    hpack4(a4[1], h+2);
    hpack4(a4[2], h+4);
    hpack4(a4[3], h+6);
    *(uint4*)&AsH[aoffs]   = *(uint4*)h;
    *(uint4*)&AsH[aoffs+4] = *(uint4*)(h+4);
}
// stage one B row-chunk (8 floats -> hi, 1x STS.128)
__device__ __forceinline__ void stage_B1(unsigned* BsH, int boffs, float4 b0, float4 b1) {
    unsigned h[4];
    hpack4(b0, h);
    hpack4(b1, h+2);
    *(uint4*)&BsH[boffs] = *(uint4*)h;
}

// 2-term step: 6 LDSM + 16 MMA per warp
__device__ __forceinline__ void mma_step_ldsm(
    float c[2][4][4], const unsigned* __restrict__ buf,
    int aoff, int boff, int pb)
{
    const unsigned* AsH = buf;
    const unsigned* AsL = buf + OFF_AL;
    const unsigned* BsH = buf + OFF_BH;
    unsigned ah0[4], al0[4], ah1[4], al1[4];
    ldsm4(AsH + aoff + pb,       ah0);
    ldsm4(AsL + aoff + pb,       al0);
    ldsm4(AsH + aoff + 320 + pb, ah1);
    ldsm4(AsL + aoff + 320 + pb, al1);
    unsigned bh01[4], bh23[4];
    ldsm4(BsH + boff + pb,       bh01);
    ldsm4(BsH + boff + 320 + pb, bh23);

    #pragma unroll
    for (int mt = 0; mt < 2; mt++) {
        const unsigned* A_h = mt ? ah1 : ah0;
        const unsigned* A_l = mt ? al1 : al0;
        #pragma unroll
        for (int nt = 0; nt < 4; nt++) {
            const unsigned* B_h = (nt < 2 ? bh01 : bh23) + (nt & 1) * 2;
            mma16(c[mt][nt], A_h, B_h);
            mma16(c[mt][nt], A_l, B_h);
        }
    }
}

// 1-term step (MoE): 4 LDSM + 8 MMA per warp
__device__ __forceinline__ void mma_step_1t(
    float c[2][4][4], const unsigned* __restrict__ buf,
    int aoff, int boff, int pb)
{
    const unsigned* AsH = buf;
    const unsigned* BsH = buf + MOFF_BH;
    unsigned ah0[4], ah1[4];
    ldsm4(AsH + aoff + pb,       ah0);
    ldsm4(AsH + aoff + 320 + pb, ah1);
    unsigned bh01[4], bh23[4];
    ldsm4(BsH + boff + pb,       bh01);
    ldsm4(BsH + boff + 320 + pb, bh23);

    #pragma unroll
    for (int mt = 0; mt < 2; mt++) {
        const unsigned* A_h = mt ? ah1 : ah0;
        #pragma unroll
        for (int nt = 0; nt < 4; nt++) {
            const unsigned* B_h = (nt < 2 ? bh01 : bh23) + (nt & 1) * 2;
            mma16(c[mt][nt], A_h, B_h);
        }
    }
}

__device__ __forceinline__ int a_ldsm_off(int wm, int lane) {
    return (wm + (lane & 15)) * ASTR + (lane >> 4) * 4;
}
__device__ __forceinline__ int b_ldsm_off(int wn, int lane) {
    return (wn + ((lane >> 4) << 3) + (lane & 7)) * ASTR + ((lane >> 3) & 1) * 4;
}

// ---------------- 2-term fp16 GEMM (projections), block 128x64, double-buffered ----------------
__global__ __launch_bounds__(256, 2) void mma_gemm(
    const float* __restrict__ A, int lda, long long sAo, long long sAi,
    const float* __restrict__ B, int ldb, long long sBo, long long sBi,
    float* __restrict__ C, int ldc, long long sCo, long long sCi,
    int M, int N, int K, int inner,
    const float* __restrict__ bias, float alpha, const float* __restrict__ res)
{
    extern __shared__ unsigned smem_dyn[];

    int z = blockIdx.z;
    int zo = z / inner, zi = z - zo * inner;
    A += zo * sAo + zi * sAi;
    B += zo * sBo + zi * sBi;
    C += zo * sCo + zi * sCi;
    if (res) res += zo * sCo + zi * sCi;

    int tid = threadIdx.x, lane = tid & 31, warp = tid >> 5;
    int g = lane >> 2, tig = lane & 3;
    int wm = (warp & 3) * 32, wn = (warp >> 2) * 32;
    int m0 = blockIdx.y * 128, n0 = blockIdx.x * 64;

    int aoff = a_ldsm_off(wm, lane);
    int boff = b_ldsm_off(wn, lane);

    int rowA, khA, aoffs, rowB, kqB, boffs;
    a_stage_coords(tid, rowA, khA, aoffs);
    b_stage_coords(tid, rowB, kqB, boffs);
    int gmA = m0 + rowA;
    bool aok = (gmA < M);
    const float* apA = A + (long long)gmA * lda + khA*16;
    const float* bpB = B + (long long)(n0 + rowB) * ldb + kqB*8;

    float c[2][4][4] = {};
    float4 aR[4];
    float4 bR[2];
    const float4 Z4 = make_float4(0,0,0,0);

    // prologue loads (k=0)
    #pragma unroll
    for (int q = 0; q < 4; q++) aR[q] = aok ? *(const float4*)(apA + q*4) : Z4;
    bR[0] = *(const float4*)(bpB);
    bR[1] = *(const float4*)(bpB + 4);

    {
        unsigned* AsH = smem_dyn;          unsigned* AsL = smem_dyn + OFF_AL;
        unsigned* BsH = smem_dyn + OFF_BH;
        stage_A2(AsH, AsL, aoffs, aR);
        stage_B1(BsH, boffs, bR[0], bR[1]);
    }
    __syncthreads();

    int sel = 0;
    for (int k0 = 0; k0 < K; k0 += 32) {
        unsigned* cb = smem_dyn + sel * BUFW;
        unsigned* nb = smem_dyn + (sel ^ 1) * BUFW;
        int k1 = k0 + 32;
        bool more = (k1 < K);

        if (more) {
            #pragma unroll
            for (int q = 0; q < 4; q++) aR[q] = aok ? *(const float4*)(apA + k1 + q*4) : Z4;
            bR[0] = *(const float4*)(bpB + k1);
            bR[1] = *(const float4*)(bpB + k1 + 4);
        }

        mma_step_ldsm(c, cb, aoff, boff, 0);
        mma_step_ldsm(c, cb, aoff, boff, 8);

        if (more) {
            unsigned* AsH = nb;          unsigned* AsL = nb + OFF_AL;
            unsigned* BsH = nb + OFF_BH;
            stage_A2(AsH, AsL, aoffs, aR);
            stage_B1(BsH, boffs, bR[0], bR[1]);
        }
        __syncthreads();
        sel ^= 1;
    }

    #pragma unroll
    for (int mt = 0; mt < 2; mt++) {
        int r0 = m0 + wm + mt*16 + g;
        #pragma unroll
        for (int nt = 0; nt < 4; nt++) {
            int col = n0 + wn + nt*8 + tig*2;
            float bv0 = bias ? bias[col]   : 0.f;
            float bv1 = bias ? bias[col+1] : 0.f;
            if (r0 < M) {
                float v0 = alpha*c[mt][nt][0] + bv0;
                float v1 = alpha*c[mt][nt][1] + bv1;
                if (res) { v0 += res[(long long)r0*ldc + col]; v1 += res[(long long)r0*ldc + col + 1]; }
                C[(long long)r0*ldc + col]     = v0;
                C[(long long)r0*ldc + col + 1] = v1;
            }
            int r1 = r0 + 8;
            if (r1 < M) {
                float v2 = alpha*c[mt][nt][2] + bv0;
                float v3 = alpha*c[mt][nt][3] + bv1;
                if (res) { v2 += res[(long long)r1*ldc + col]; v3 += res[(long long)r1*ldc + col + 1]; }
                C[(long long)r1*ldc + col]     = v2;
                C[(long long)r1*ldc + col + 1] = v3;
            }
        }
    }
}

// ---------------- fused flash attention (fp16: Q split, K/V/P single) ----------------
#define FQH 0
#define FQL 4608
#define FKH 9216
#define FVH 11520
#define FA_SMEM (13824*4)

__global__ __launch_bounds__(256, 2) void fa_k(
    const float* __restrict__ Q, int ldq,
    const float* __restrict__ K, const float* __restrict__ V, int ldkv,
    float* __restrict__ O, int ldo, int kvlen)
{
    extern __shared__ unsigned smem_dyn[];
    unsigned* QsH = smem_dyn + FQH; unsigned* QsL = smem_dyn + FQL;
    unsigned* KsH = smem_dyn + FKH;
    unsigned* VsH = smem_dyn + FVH;

    int tid = threadIdx.x, lane = tid & 31, warp = tid >> 5;
    int g = lane >> 2, tig = lane & 3;
    int b = blockIdx.y >> 4, h = blockIdx.y & 15;
    long long qrow0 = (long long)b * NQv + blockIdx.x * 128;
    Q += qrow0 * ldq + h * 64;
    O += qrow0 * ldo + h * 64;
    K += (long long)b * kvlen * ldkv + h * 64;
    V += (long long)b * kvlen * ldkv + h * 64;

    int aoffq = (warp*16 + (lane & 15)) * 36 + (lane >> 4) * 4;
    int boff  = (((lane >> 4) << 3) + (lane & 7)) * 36 + ((lane >> 3) & 1) * 4;

    float c_o[8][4] = {};
    float m0 = -3.4e38f, m1 = -3.4e38f, l0 = 0.f, l1 = 0.f;

    {
        int qrow = tid >> 1, qhalf = tid & 1;
        const float* qp = Q + (long long)qrow * ldq + qhalf * 32;
        int base = qrow * 36 + qhalf * 16;
        #pragma unroll
        for (int i = 0; i < 2; i++) {
            float4 v0 = *(const float4*)(qp + i*16);
            float4 v1 = *(const float4*)(qp + i*16 + 4);
            float4 v2 = *(const float4*)(qp + i*16 + 8);
            float4 v3 = *(const float4*)(qp + i*16 + 12);
            unsigned h4[4], l4[4];
            hsplit4(v0, h4, l4); hsplit4(v1, h4+2, l4+2);
            *(uint4*)&QsH[base + i*8] = *(uint4*)h4;
            *(uint4*)&QsL[base + i*8] = *(uint4*)l4;
            hsplit4(v2, h4, l4); hsplit4(v3, h4+2, l4+2);
            *(uint4*)&QsH[base + i*8 + 4] = *(uint4*)h4;
            *(uint4*)&QsL[base + i*8 + 4] = *(uint4*)l4;
        }
    }

    for (int kv0 = 0; kv0 < kvlen; kv0 += 64) {
        __syncthreads();
        {
            int krow = tid >> 2, kq = tid & 3;
            const float* kp = K + (long long)(kv0 + krow) * ldkv + kq * 16;
            float4 v0 = *(const float4*)(kp);
            float4 v1 = *(const float4*)(kp + 4);
            float4 v2 = *(const float4*)(kp + 8);
            float4 v3 = *(const float4*)(kp + 12);
            int base = krow * 36 + kq * 8;
            unsigned h4[4];
            hpack4(v0, h4); hpack4(v1, h4+2);
            *(uint4*)&KsH[base] = *(uint4*)h4;
            hpack4(v2, h4); hpack4(v3, h4+2);
            *(uint4*)&KsH[base + 4] = *(uint4*)h4;
        }
        {
            int vc = tid & 63, vg = tid >> 6;
            float vv[16];
            #pragma unroll
            for (int j = 0; j < 16; j++)
                vv[j] = V[(long long)(kv0 + vg*16 + j) * ldkv + vc];
            int base = vc * 36 + vg * 8;
            #pragma unroll
            for (int half = 0; half < 2; half++) {
                unsigned h4[4];
                h4[0] = hpack2(vv[half*8+0], vv[half*8+1]);
                h4[1] = hpack2(vv[half*8+2], vv[half*8+3]);
                h4[2] = hpack2(vv[half*8+4], vv[half*8+5]);
                h4[3] = hpack2(vv[half*8+6], vv[half*8+7]);
                *(uint4*)&VsH[base + half*4] = *(uint4*)h4;
            }
        }
        __syncthreads();

        float c_s[8][4] = {};
        #pragma unroll
        for (int kp = 0; kp < 4; kp++) {
            unsigned qh[4], ql[4];
            ldsm4(QsH + aoffq + kp*8, qh);
            ldsm4(QsL + aoffq + kp*8, ql);
            #pragma unroll
            for (int gi = 0; gi < 4; gi++) {
                unsigned kh[4];
                ldsm4(KsH + boff + gi*576 + kp*8, kh);
                #pragma unroll
                for (int h2 = 0; h2 < 2; h2++) {
                    int nt = gi*2 + h2;
                    mma16(c_s[nt], qh, kh + h2*2);
                    mma16(c_s[nt], ql, kh + h2*2);
                }
            }
        }

        float t0 = -3.4e38f, t1 = -3.4e38f;
        #pragma unroll
        for (int nt = 0; nt < 8; nt++) {
            #pragma unroll
            for (int j = 0; j < 4; j++) c_s[nt][j] *= 0.125f;
            t0 = fmaxf(t0, fmaxf(c_s[nt][0], c_s[nt][1]));
            t1 = fmaxf(t1, fmaxf(c_s[nt][2], c_s[nt][3]));
        }
        t0 = fmaxf(t0, __shfl_xor_sync(0xffffffffu, t0, 1));
        t0 = fmaxf(t0, __shfl_xor_sync(0xffffffffu, t0, 2));
        t1 = fmaxf(t1, __shfl_xor_sync(0xffffffffu, t1, 1));
        t1 = fmaxf(t1, __shfl_xor_sync(0xffffffffu, t1, 2));
        float mn0 = fmaxf(m0, t0), mn1 = fmaxf(m1, t1);
        float es0 = __expf(m0 - mn0), es1 = __expf(m1 - mn1);
        float s0 = 0.f, s1 = 0.f;
        #pragma unroll
        for (int nt = 0; nt < 8; nt++) {
            c_s[nt][0] = __expf(c_s[nt][0] - mn0); s0 += c_s[nt][0];
            c_s[nt][1] = __expf(c_s[nt][1] - mn0); s0 += c_s[nt][1];
            c_s[nt][2] = __expf(c_s[nt][2] - mn1); s1 += c_s[nt][2];
            c_s[nt][3] = __expf(c_s[nt][3] - mn1); s1 += c_s[nt][3];
        }
        s0 += __shfl_xor_sync(0xffffffffu, s0, 1);
        s0 += __shfl_xor_sync(0xffffffffu, s0, 2);
        s1 += __shfl_xor_sync(0xffffffffu, s1, 1);
        s1 += __shfl_xor_sync(0xffffffffu, s1, 2);
        l0 = l0 * es0 + s0;  l1 = l1 * es1 + s1;
        m0 = mn0; m1 = mn1;
        #pragma unroll
        for (int nt = 0; nt < 8; nt++) {
            c_o[nt][0] *= es0; c_o[nt][1] *= es0;
            c_o[nt][2] *= es1; c_o[nt][3] *= es1;
        }

        #pragma unroll
        for (int kk = 0; kk < 4; kk++) {
            unsigned pa[4];
            pa[0] = hpack2(c_s[2*kk][0],   c_s[2*kk][1]);
            pa[1] = hpack2(c_s[2*kk][2],   c_s[2*kk][3]);
            pa[2] = hpack2(c_s[2*kk+1][0], c_s[2*kk+1][1]);
            pa[3] = hpack2(c_s[2*kk+1][2], c_s[2*kk+1][3]);
            #pragma unroll
            for (int gi = 0; gi < 4; gi++) {
                unsigned vh[4];
                ldsm4(VsH + boff + gi*576 + kk*8, vh);
                #pragma unroll
                for (int h2 = 0; h2 < 2; h2++) {
                    int nt = gi*2 + h2;
                    mma16(c_o[nt], pa, vh + h2*2);
                }
            }
        }
    }

    float inv0 = 1.0f / l0, inv1 = 1.0f / l1;
    int r0 = warp*16 + g, r1 = r0 + 8;
    #pragma unroll
    for (int nt = 0; nt < 8; nt++) {
        int col = nt*8 + tig*2;
        O[(long long)r0*ldo + col]     = c_o[nt][0]*inv0;
        O[(long long)r0*ldo + col + 1] = c_o[nt][1]*inv0;
        O[(long long)r1*ldo + col]     = c_o[nt][2]*inv1;
        O[(long long)r1*ldo + col + 1] = c_o[nt][3]*inv1;
    }
}

// ---------------- JAX threefry2x32 / normal ----------------
__device__ __forceinline__ void threefry42(unsigned c0, unsigned c1, unsigned& o0, unsigned& o1) {
    const unsigned k0 = 0u, k1 = 42u;
    const unsigned k2 = 0x1BD11BDAu ^ k0 ^ k1;
    unsigned x0 = c0 + k0, x1 = c1 + k1;
#define TF_R(r) { x0 += x1; x1 = (x1 << r) | (x1 >> (32 - r)); x1 ^= x0; }
    TF_R(13) TF_R(15) TF_R(26) TF_R(6)   x0 += k1; x1 += k2 + 1u;
    TF_R(17) TF_R(29) TF_R(16) TF_R(24)  x0 += k2; x1 += k0 + 2u;
    TF_R(13) TF_R(15) TF_R(26) TF_R(6)   x0 += k0; x1 += k1 + 3u;
    TF_R(17) TF_R(29) TF_R(16) TF_R(24)  x0 += k1; x1 += k2 + 4u;
    TF_R(13) TF_R(15) TF_R(26) TF_R(6)   x0 += k2; x1 += k0 + 5u;
#undef TF_R
    o0 = x0; o1 = x1;
}

__device__ __forceinline__ float erfinv_f(float x) {
    float w = -log1pf(__fmul_rn(-x, x));
    float p;
    if (w < 5.0f) {
        w = __fadd_rn(w, -2.5f);
        p = 2.81022636e-08f;
        p = __fadd_rn(__fmul_rn(p, w),  3.43273939e-07f);
        p = __fadd_rn(__fmul_rn(p, w), -3.5233877e-06f);
        p = __fadd_rn(__fmul_rn(p, w), -4.39150654e-06f);
        p = __fadd_rn(__fmul_rn(p, w),  0.00021858087f);
        p = __fadd_rn(__fmul_rn(p, w), -0.00125372503f);
        p = __fadd_rn(__fmul_rn(p, w), -0.00417768164f);
        p = __fadd_rn(__fmul_rn(p, w),  0.246640727f);
        p = __fadd_rn(__fmul_rn(p, w),  1.50140941f);
    } else {
        w = __fadd_rn(sqrtf(w), -3.0f);
        p = -0.000200214257f;
        p = __fadd_rn(__fmul_rn(p, w),  0.000100950558f);
        p = __fadd_rn(__fmul_rn(p, w),  0.00134934322f);
        p = __fadd_rn(__fmul_rn(p, w), -0.00367342844f);
        p = __fadd_rn(__fmul_rn(p, w),  0.00573950773f);
        p = __fadd_rn(__fmul_rn(p, w), -0.0076224613f);
        p = __fadd_rn(__fmul_rn(p, w),  0.00943887047f);
        p = __fadd_rn(__fmul_rn(p, w),  1.00167406f);
        p = __fadd_rn(__fmul_rn(p, w),  2.83297682f);
    }
    return __fmul_rn(p, x);
}

__device__ __forceinline__ float jax_normal(int i) {
    unsigned o0, o1;
    threefry42(0u, (unsigned)i, o0, o1);
    unsigned bits = o0 ^ o1;
    unsigned fb = (bits >> 9) | 0x3f800000u;
    float u01 = __fadd_rn(__uint_as_float(fb), -1.0f);
    const float lo = -0.99999994f;
    float u = __fadd_rn(__fmul_rn(u01, 2.0f), lo);
    u = fmaxf(lo, u);
    return __fmul_rn(1.41421354f, erfinv_f(u));
}

// ---------------- MoE router ----------------
__global__ void zero_counts_k() { if (threadIdx.x < Ev) g_counts[threadIdx.x] = 0; }

__global__ void router_k(const float* __restrict__ xm,
                         const float* __restrict__ rw, const float* __restrict__ rb,
                         const float* __restrict__ nw, const float* __restrict__ nb) {
    int t = blockIdx.x;
    int tid = threadIdx.x;
    int w = tid >> 5, lane = tid & 31;
    __shared__ float sl[8], sn[8];
    const float* xr = xm + (long long)t * 1024;
    const float* rwe = rw + w * 1024;
    const float* nwe = nw + w * 1024;
    float sr = 0.f, s_n = 0.f;
    for (int d = lane; d < 1024; d += 32) {
        float xv = xr[d];
        sr  += xv * rwe[d];
        s_n += xv * nwe[d];
    }
    #pragma unroll
    for (int o = 16; o; o >>= 1) {
        sr  += __shfl_down_sync(0xffffffffu, sr, o);
        s_n += __shfl_down_sync(0xffffffffu, s_n, o);
    }
    if (lane == 0) { sl[w] = sr + rb[w]; sn[w] = s_n + nb[w]; }
    __syncthreads();
    if (tid == 0) {
        float noisy[8];
        #pragma unroll
        for (int e = 0; e < 8; e++) {
            float nrm = jax_normal(t * 8 + e);
            float zz = sn[e];
            float sp = fmaxf(zz, 0.f) + log1pf(expf(-fabsf(zz)));
            noisy[e] = sl[e] + nrm * sp;
        }
        int i1 = 0;
        #pragma unroll
        for (int e = 1; e < 8; e++) if (noisy[e] > noisy[i1]) i1 = e;
        int i2 = (i1 == 0) ? 1 : 0;
        #pragma unroll
        for (int e = 0; e < 8; e++) if (e != i1 && noisy[e] > noisy[i2]) i2 = e;
        float mx = noisy[i1];
        float e1 = expf(noisy[i1] - mx);
        float e2 = expf(noisy[i2] - mx);
        float Z  = e1 + e2;
        g_probs[2*t]   = e1 / Z;
        g_probs[2*t+1] = e2 / Z;
        int p1 = atomicAdd(&g_counts[i1], 1); g_elist[i1 * MAXTOK + p1] = 2*t;
        int p2 = atomicAdd(&g_counts[i2], 1); g_elist[i2 * MAXTOK + p2] = 2*t + 1;
    }
}

// ---------------- MoE 1-term fp16 GEMMs ----------------
// GEMM1: h = gelu(xm @ w1 + b1), output fp16 to g_hh
__global__ __launch_bounds__(256, 2) void moe_mma1(const float* __restrict__ xm,
                                                   const float* __restrict__ w1,
                                                   const float* __restrict__ b1) {
    extern __shared__ unsigned smem_dyn[];
    __shared__ int slots[128];

    int e = blockIdx.z;
    int cnt = g_counts[e];
    int m0 = blockIdx.y * 128;
    if (m0 >= cnt) return;
    int n0 = blockIdx.x * 64;

    int tid = threadIdx.x, lane = tid & 31, warp = tid >> 5;
    int g = lane >> 2, tig = lane & 3;
    int wm = (warp & 3) * 32, wn = (warp >> 2) * 32;
    if (tid < 128) slots[tid] = (m0 + tid < cnt) ? g_elist[e * MAXTOK + m0 + tid] : -1;
    __syncthreads();

    int aoff = a_ldsm_off(wm, lane);
    int boff = b_ldsm_off(wn, lane);

    int rowA, khA, aoffs;
    a_stage_coords(tid, rowA, khA, aoffs);
    int sgl = slots[rowA];
    long long abase = (sgl >= 0) ? ((long long)(sgl >> 1) * 1024) : 0;
    const float* apA = xm + abase + khA*16;

    const float* Be = w1 + (long long)e * 1024 * 4096;
    int bnc = tid & 63, bkg = tid >> 6;
    int boffs = bnc*ASTR + bkg*4;

    float c[2][4][4] = {};
    float4 aR[4];
    float  bf[8];
    const float4 Z4 = make_float4(0,0,0,0);

    #pragma unroll
    for (int q = 0; q < 4; q++) aR[q] = (sgl >= 0) ? *(const float4*)(apA + q*4) : Z4;
    #pragma unroll
    for (int j = 0; j < 8; j++)
        bf[j] = Be[(long long)(bkg*8 + j) * 4096 + n0 + bnc];

    {
        unsigned* AsH = smem_dyn;  unsigned* BsH = smem_dyn + MOFF_BH;
        stage_A1(AsH, aoffs, aR);
        unsigned h4[4];
        h4[0] = hpack2(bf[0], bf[1]); h4[1] = hpack2(bf[2], bf[3]);
        h4[2] = hpack2(bf[4], bf[5]); h4[3] = hpack2(bf[6], bf[7]);
        *(uint4*)&BsH[boffs] = *(uint4*)h4;
    }
    __syncthreads();

    int sel = 0;
    for (int k0 = 0; k0 < 1024; k0 += 32) {
        unsigned* cb = smem_dyn + sel * MBUFW;
        unsigned* nb = smem_dyn + (sel ^ 1) * MBUFW;
        int k1 = k0 + 32;
        bool more = (k1 < 1024);
        if (more) {
            #pragma unroll
            for (int q = 0; q < 4; q++) aR[q] = (sgl >= 0) ? *(const float4*)(apA + k1 + q*4) : Z4;
            #pragma unroll
            for (int j = 0; j < 8; j++)
                bf[j] = Be[(long long)(k1 + bkg*8 + j) * 4096 + n0 + bnc];
        }
        mma_step_1t(c, cb, aoff, boff, 0);
        mma_step_1t(c, cb, aoff, boff, 8);
        if (more) {
            unsigned* AsH = nb;  unsigned* BsH = nb + MOFF_BH;
            stage_A1(AsH, aoffs, aR);
            unsigned h4[4];
            h4[0] = hpack2(bf[0], bf[1]); h4[1] = hpack2(bf[2], bf[3]);
            h4[2] = hpack2(bf[4], bf[5]); h4[3] = hpack2(bf[6], bf[7]);
            *(uint4*)&BsH[boffs] = *(uint4*)h4;
        }
        __syncthreads();
        sel ^= 1;
    }

    #pragma unroll
    for (int mt = 0; mt < 2; mt++) {
        int lr0 = wm + mt*16 + g;
        int s0 = slots[lr0], s1 = slots[lr0 + 8];
        #pragma unroll
        for (int nt = 0; nt < 4; nt++) {
            int col = n0 + wn + nt*8 + tig*2;
            float bv0 = b1[e*4096 + col], bv1 = b1[e*4096 + col + 1];
            if (s0 >= 0) {
                float v0 = c[mt][nt][0] + bv0;
                float v1 = c[mt][nt][1] + bv1;
                v0 = 0.5f * v0 * (1.0f + erff(v0 * 0.70710677f));
                v1 = 0.5f * v1 * (1.0f + erff(v1 * 0.70710677f));
                *(__half2*)&g_hh[(long long)s0*4096 + col] = __floats2half2_rn(v0, v1);
            }
            if (s1 >= 0) {
                float v2 = c[mt][nt][2] + bv0;
                float v3 = c[mt][nt][3] + bv1;
                v2 = 0.5f * v2 * (1.0f + erff(v2 * 0.70710677f));
                v3 = 0.5f * v3 * (1.0f + erff(v3 * 0.70710677f));
                *(__half2*)&g_hh[(long long)s1*4096 + col] = __floats2half2_rn(v2, v3);
            }
        }
    }
}

// GEMM2: eo = h @ w2 + b2  (h fp16 in g_hh: raw uint4 staging, zero conversion)
__global__ __launch_bounds__(256, 2) void moe_mma2(const float* __restrict__ w2,
                                                   const float* __restrict__ b2) {
    extern __shared__ unsigned smem_dyn[];
    __shared__ int slots[128];

    int e = blockIdx.z;
    int cnt = g_counts[e];
    int m0 = blockIdx.y * 128;
    if (m0 >= cnt) return;
    int n0 = blockIdx.x * 64;

    int tid = threadIdx.x, lane = tid & 31, warp = tid >> 5;
    int g = lane >> 2, tig = lane & 3;
    int wm = (warp & 3) * 32, wn = (warp >> 2) * 32;
    if (tid < 128) slots[tid] = (m0 + tid < cnt) ? g_elist[e * MAXTOK + m0 + tid] : -1;
    __syncthreads();

    int aoff = a_ldsm_off(wm, lane);
    int boff = b_ldsm_off(wn, lane);

    int rowA, khA, aoffs;
    a_stage_coords(tid, rowA, khA, aoffs);
    int sgl = slots[rowA];
    long long abase = (sgl >= 0) ? ((long long)sgl * 4096) : 0;
    const __half* apA = g_hh + abase + khA*16;

    const float* Be = w2 + (long long)e * 4096 * 1024;
    int bnc = tid & 63, bkg = tid >> 6;
    int boffs = bnc*ASTR + bkg*4;

    float c[2][4][4] = {};
    uint4 aU[2];
    float bf[8];
    const uint4 Z4u = make_uint4(0,0,0,0);

    aU[0] = (sgl >= 0) ? *(const uint4*)(apA)     : Z4u;
    aU[1] = (sgl >= 0) ? *(const uint4*)(apA + 8) : Z4u;
    #pragma unroll
    for (int j = 0; j < 8; j++)
        bf[j] = Be[(long long)(bkg*8 + j) * 1024 + n0 + bnc];

    {
        unsigned* AsH = smem_dyn;  unsigned* BsH = smem_dyn + MOFF_BH;
        *(uint4*)&AsH[aoffs]   = aU[0];
        *(uint4*)&AsH[aoffs+4] = aU[1];
        unsigned h4[4];
        h4[0] = hpack2(bf[0], bf[1]); h4[1] = hpack2(bf[2], bf[3]);
        h4[2] = hpack2(bf[4], bf[5]); h4[3] = hpack2(bf[6], bf[7]);
        *(uint4*)&BsH[boffs] = *(uint4*)h4;
    }
    __syncthreads();

    int sel = 0;
    for (int k0 = 0; k0 < 4096; k0 += 32) {
        unsigned* cb = smem_dyn + sel * MBUFW;
        unsigned* nb = smem_dyn + (sel ^ 1) * MBUFW;
        int k1 = k0 + 32;
        bool more = (k1 < 4096);
        if (more) {
            aU[0] = (sgl >= 0) ? *(const uint4*)(apA + k1)     : Z4u;
            aU[1] = (sgl >= 0) ? *(const uint4*)(apA + k1 + 8) : Z4u;
            #pragma unroll
            for (int j = 0; j < 8; j++)
                bf[j] = Be[(long long)(k1 + bkg*8 + j) * 1024 + n0 + bnc];
        }
        mma_step_1t(c, cb, aoff, boff, 0);
        mma_step_1t(c, cb, aoff, boff, 8);
        if (more) {
            unsigned* AsH = nb;  unsigned* BsH = nb + MOFF_BH;
            *(uint4*)&AsH[aoffs]   = aU[0];
            *(uint4*)&AsH[aoffs+4] = aU[1];
            unsigned h4[4];
            h4[0] = hpack2(bf[0], bf[1]); h4[1] = hpack2(bf[2], bf[3]);
            h4[2] = hpack2(bf[4], bf[5]); h4[3] = hpack2(bf[6], bf[7]);
            *(uint4*)&BsH[boffs] = *(uint4*)h4;
        }
        __syncthreads();
        sel ^= 1;
    }

    #pragma unroll
    for (int mt = 0; mt < 2; mt++) {
        int lr0 = wm + mt*16 + g;
        int s0 = slots[lr0], s1 = slots[lr0 + 8];
        #pragma unroll
        for (int nt = 0; nt < 4; nt++) {
            int col = n0 + wn + nt*8 + tig*2;
            float bv0 = b2[e*1024 + col], bv1 = b2[e*1024 + col + 1];
            if (s0 >= 0) {
                g_eo[(long long)s0*1024 + col]     = c[mt][nt][0] + bv0;
                g_eo[(long long)s0*1024 + col + 1] = c[mt][nt][1] + bv1;
            }
            if (s1 >= 0) {
                g_eo[(long long)s1*1024 + col]     = c[mt][nt][2] + bv0;
                g_eo[(long long)s1*1024 + col + 1] = c[mt][nt][3] + bv1;
            }
        }
    }
}

__global__ void combine_k(const float* __restrict__ x, float* __restrict__ out) {
    int idx = blockIdx.x * 256 + threadIdx.x;
    int t = idx >> 10, d = idx & 1023;
    float v = x[idx];
    v += g_probs[2*t]     * g_eo[(long long)(2*t)     * 1024 + d];
    v += g_probs[2*t + 1] * g_eo[(long long)(2*t + 1) * 1024 + d];
    out[idx] = v;
}

// ---------------- launcher ----------------
extern "C" void kernel_launch(void* const* d_in, const int* in_sizes, int n_in,
                              void* d_out, int out_size) {
    const float* q        = (const float*)d_in[0];
    const float* kv       = (const float*)d_in[1];
    const float* ln_cq_g  = (const float*)d_in[2];
    const float* ln_cq_b  = (const float*)d_in[3];
    const float* ln_ckv_g = (const float*)d_in[4];
    const float* ln_ckv_b = (const float*)d_in[5];
    const float* ln_s_g   = (const float*)d_in[6];
    const float* ln_s_b   = (const float*)d_in[7];
    const float* ln_m_g   = (const float*)d_in[8];
    const float* ln_m_b   = (const float*)d_in[9];
    const float* ca_in_w  = (const float*)d_in[10];
    const float* ca_in_b  = (const float*)d_in[11];
    const float* ca_out_w = (const float*)d_in[12];
    const float* ca_out_b = (const float*)d_in[13];
    const float* sa_in_w  = (const float*)d_in[14];
    const float* sa_in_b  = (const float*)d_in[15];
    const float* sa_out_w = (const float*)d_in[16];
    const float* sa_out_b = (const float*)d_in[17];
    const float* moe_rw   = (const float*)d_in[18];
    const float* moe_rb   = (const float*)d_in[19];
    const float* moe_nw   = (const float*)d_in[20];
    const float* moe_nb   = (const float*)d_in[21];
    const float* moe_w1   = (const float*)d_in[22];
    const float* moe_b1   = (const float*)d_in[23];
    const float* moe_w2   = (const float*)d_in[24];
    const float* moe_b2   = (const float*)d_in[25];
    float* out = (float*)d_out;

    float *p_x, *p_ln1, *p_lnkv, *p_qp, *p_kvp, *p_ao;
    cudaGetSymbolAddress((void**)&p_x,    g_x);
    cudaGetSymbolAddress((void**)&p_ln1,  g_ln1);
    cudaGetSymbolAddress((void**)&p_lnkv, g_lnkv);
    cudaGetSymbolAddress((void**)&p_qp,   g_qp);
    cudaGetSymbolAddress((void**)&p_kvp,  g_kvp);
    cudaGetSymbolAddress((void**)&p_ao,   g_ao);

    cudaFuncSetAttribute(mma_gemm, cudaFuncAttributeMaxDynamicSharedMemorySize, DSMEM_BYTES);
    cudaFuncSetAttribute(moe_mma1, cudaFuncAttributeMaxDynamicSharedMemorySize, MDSMEM_BYTES);
    cudaFuncSetAttribute(moe_mma2, cudaFuncAttributeMaxDynamicSharedMemorySize, MDSMEM_BYTES);
    cudaFuncSetAttribute(fa_k,     cudaFuncAttributeMaxDynamicSharedMemorySize, FA_SMEM);

    const long long ZL = 0;

    // ===== Cross-attention =====
    ln_k<<<TQ, 256>>>(q,  p_ln1,  ln_cq_g,  ln_cq_b);
    ln_k<<<TKV, 256>>>(kv, p_lnkv, ln_ckv_g, ln_ckv_b);

    mma_gemm<<<dim3(16, 16, 1), 256, DSMEM_BYTES>>>(p_ln1, 1024, ZL, ZL,
        ca_in_w, 1024, ZL, ZL, p_qp, 1024, ZL, ZL,
        TQ, 1024, 1024, 1, ca_in_b, 1.0f, nullptr);
    mma_gemm<<<dim3(32, 32, 1), 256, DSMEM_BYTES>>>(p_lnkv, 1024, ZL, ZL,
        ca_in_w + 1024*1024, 1024, ZL, ZL, p_kvp, 2048, ZL, ZL,
        TKV, 2048, 1024, 1, ca_in_b + 1024, 1.0f, nullptr);

    fa_k<<<dim3(8, 32), 256, FA_SMEM>>>(p_qp, 1024, p_kvp, p_kvp + 1024, 2048,
                                        p_ao, 1024, NKVv);

    mma_gemm<<<dim3(16, 16, 1), 256, DSMEM_BYTES>>>(p_ao, 1024, ZL, ZL,
        ca_out_w, 1024, ZL, ZL, p_x, 1024, ZL, ZL,
        TQ, 1024, 1024, 1, ca_out_b, 1.0f, q);

    // ===== Self-attention =====
    ln_k<<<TQ, 256>>>(p_x, p_ln1, ln_s_g, ln_s_b);
    mma_gemm<<<dim3(48, 16, 1), 256, DSMEM_BYTES>>>(p_ln1, 1024, ZL, ZL,
        sa_in_w, 1024, ZL, ZL, p_kvp, 3072, ZL, ZL,
        TQ, 3072, 1024, 1, sa_in_b, 1.0f, nullptr);

    fa_k<<<dim3(8, 32), 256, FA_SMEM>>>(p_kvp, 3072, p_kvp + 1024, p_kvp + 2048, 3072,
                                        p_ao, 1024, NQv);

    mma_gemm<<<dim3(16, 16, 1), 256, DSMEM_BYTES>>>(p_ao, 1024, ZL, ZL,
        sa_out_w, 1024, ZL, ZL, p_x, 1024, ZL, ZL,
        TQ, 1024, 1024, 1, sa_out_b, 1.0f, p_x);

    // ===== MoE =====
    ln_k<<<TQ, 256>>>(p_x, p_ln1, ln_m_g, ln_m_b);
    zero_counts_k<<<1, 32>>>();
    router_k<<<TQ, 256>>>(p_ln1, moe_rw, moe_rb, moe_nw, moe_nb);
    moe_mma1<<<dim3(64, 16, 8), 256, MDSMEM_BYTES>>>(p_ln1, moe_w1, moe_b1);
    moe_mma2<<<dim3(16, 16, 8), 256, MDSMEM_BYTES>>>(moe_w2, moe_b2);
    combine_k<<<(TQ*Dv)/256, 256>>>(p_x, out);
}

// round 17
// speedup vs baseline: 1.1418x; 1.1418x over previous
#include <cuda_runtime.h>
#include <cuda_fp16.h>
#include <math.h>
#include <stdint.h>

// Problem dims
#define Bv    2
#define NQv   1024
#define NKVv  2048
#define Dv    1024
#define Hv    16
#define DHv   64
#define Ev    8
#define FFv   4096
#define TQ    (Bv*NQv)
#define TKV   (Bv*NKVv)
#define MAXTOK 2048

// ---------------- scratch ----------------
__device__ float  g_x[TQ*Dv];
__device__ float  g_ln1[TQ*Dv];
__device__ float  g_lnkv[TKV*Dv];
__device__ float  g_qp[TQ*Dv];
__device__ float  g_kvp[TKV*2048];
__device__ float  g_ao[TQ*Dv];
__device__ __half g_hh[(size_t)TQ*2*FFv];    // MoE hidden, fp16
__device__ float  g_eo[(size_t)TQ*2*Dv];
__device__ float  g_probs[TQ*2];
__device__ int    g_counts[Ev];
__device__ int    g_elist[Ev*MAXTOK];

// ---------------- layernorm ----------------
__global__ void ln_k(const float* __restrict__ x, float* __restrict__ y,
                     const float* __restrict__ g, const float* __restrict__ b) {
    long row = blockIdx.x;
    const float* xr = x + row * 1024;
    float* yr = y + row * 1024;
    __shared__ float sm[1024];
    __shared__ float red[256];
    int tid = threadIdx.x;
    float s = 0.f;
    #pragma unroll
    for (int i = 0; i < 4; i++) { float v = xr[tid + (i<<8)]; sm[tid + (i<<8)] = v; s += v; }
    red[tid] = s; __syncthreads();
    for (int st = 128; st > 0; st >>= 1) { if (tid < st) red[tid] += red[tid + st]; __syncthreads(); }
    float mean = red[0] * (1.0f/1024.0f); __syncthreads();
    float s2 = 0.f;
    #pragma unroll
    for (int i = 0; i < 4; i++) { float d = sm[tid + (i<<8)] - mean; s2 += d*d; }
    red[tid] = s2; __syncthreads();
    for (int st = 128; st > 0; st >>= 1) { if (tid < st) red[tid] += red[tid + st]; __syncthreads(); }
    float var = red[0] * (1.0f/1024.0f);
    float rstd = rsqrtf(var + 1e-5f);
    #pragma unroll
    for (int i = 0; i < 4; i++) { int c = tid + (i<<8); yr[c] = (sm[c]-mean)*rstd*g[c] + b[c]; }
}

// ---------------- fp16 pack/split helpers ----------------
__device__ __forceinline__ unsigned hpack2(float x0, float x1) {
    __half2 h = __floats2half2_rn(x0, x1);
    return *(unsigned*)&h;
}
__device__ __forceinline__ uint2 hsplit2(float x0, float x1) {
    unsigned h = hpack2(x0, x1);
    __half2 hh = *(__half2*)&h;
    float r0 = x0 - __low2float(hh);
    float r1 = x1 - __high2float(hh);
    return make_uint2(h, hpack2(r0, r1));
}
__device__ __forceinline__ void hsplit4(float4 v, unsigned* h2, unsigned* l2) {
    uint2 p0 = hsplit2(v.x, v.y);
    uint2 p1 = hsplit2(v.z, v.w);
    h2[0] = p0.x; h2[1] = p1.x;
    l2[0] = p0.y; l2[1] = p1.y;
}
__device__ __forceinline__ void hpack4(float4 v, unsigned* h2) {
    h2[0] = hpack2(v.x, v.y);
    h2[1] = hpack2(v.z, v.w);
}

__device__ __forceinline__ void mma16(float* c, const unsigned* a, const unsigned* b) {
    asm volatile("mma.sync.aligned.m16n8k16.row.col.f32.f16.f16.f32 "
        "{%0,%1,%2,%3},{%4,%5,%6,%7},{%8,%9},{%0,%1,%2,%3};"
        : "+f"(c[0]), "+f"(c[1]), "+f"(c[2]), "+f"(c[3])
        : "r"(a[0]), "r"(a[1]), "r"(a[2]), "r"(a[3]), "r"(b[0]), "r"(b[1]));
}

__device__ __forceinline__ void ldsm4(const unsigned* p, unsigned* r) {
    unsigned addr = (unsigned)__cvta_generic_to_shared(p);
    asm volatile("ldmatrix.sync.aligned.m8n8.x4.shared.b16 {%0,%1,%2,%3}, [%4];"
        : "=r"(r[0]), "=r"(r[1]), "=r"(r[2]), "=r"(r[3]) : "r"(addr));
}
__device__ __forceinline__ void ldsm4t(const unsigned* p, unsigned* r) {
    unsigned addr = (unsigned)__cvta_generic_to_shared(p);
    asm volatile("ldmatrix.sync.aligned.m8n8.x4.trans.shared.b16 {%0,%1,%2,%3}, [%4];"
        : "=r"(r[0]), "=r"(r[1]), "=r"(r[2]), "=r"(r[3]) : "r"(addr));
}

// Unified GEMM smem layout: [row][kpair 0..15] stride 20 words
#define ASTR 20
// 2-term buffers (projections): A hi+lo, B hi
#define BUFW 6400
#define OFF_AL 2560
#define OFF_BH 5120
#define DSMEM_BYTES (2*BUFW*4)
// 1-term buffers (MoE): A hi, B hi
#define MBUFW 3840
#define MOFF_BH 2560
#define MDSMEM_BYTES (2*MBUFW*4)

// 2-term step: 6 LDSM + 16 MMA per warp
__device__ __forceinline__ void mma_step_ldsm(
    float c[2][4][4], const unsigned* __restrict__ buf,
    int aoff, int boff, int pb)
{
    const unsigned* AsH = buf;
    const unsigned* AsL = buf + OFF_AL;
    const unsigned* BsH = buf + OFF_BH;
    unsigned ah0[4], al0[4], ah1[4], al1[4];
    ldsm4(AsH + aoff + pb,       ah0);
    ldsm4(AsL + aoff + pb,       al0);
    ldsm4(AsH + aoff + 320 + pb, ah1);
    ldsm4(AsL + aoff + 320 + pb, al1);
    unsigned bh01[4], bh23[4];
    ldsm4(BsH + boff + pb,       bh01);
    ldsm4(BsH + boff + 320 + pb, bh23);

    #pragma unroll
    for (int mt = 0; mt < 2; mt++) {
        const unsigned* A_h = mt ? ah1 : ah0;
        const unsigned* A_l = mt ? al1 : al0;
        #pragma unroll
        for (int nt = 0; nt < 4; nt++) {
            const unsigned* B_h = (nt < 2 ? bh01 : bh23) + (nt & 1) * 2;
            mma16(c[mt][nt], A_h, B_h);
            mma16(c[mt][nt], A_l, B_h);
        }
    }
}

// 1-term step (MoE): 4 LDSM + 8 MMA per warp
__device__ __forceinline__ void mma_step_1t(
    float c[2][4][4], const unsigned* __restrict__ buf,
    int aoff, int boff, int pb)
{
    const unsigned* AsH = buf;
    const unsigned* BsH = buf + MOFF_BH;
    unsigned ah0[4], ah1[4];
    ldsm4(AsH + aoff + pb,       ah0);
    ldsm4(AsH + aoff + 320 + pb, ah1);
    unsigned bh01[4], bh23[4];
    ldsm4(BsH + boff + pb,       bh01);
    ldsm4(BsH + boff + 320 + pb, bh23);

    #pragma unroll
    for (int mt = 0; mt < 2; mt++) {
        const unsigned* A_h = mt ? ah1 : ah0;
        #pragma unroll
        for (int nt = 0; nt < 4; nt++) {
            const unsigned* B_h = (nt < 2 ? bh01 : bh23) + (nt & 1) * 2;
            mma16(c[mt][nt], A_h, B_h);
        }
    }
}

__device__ __forceinline__ int a_ldsm_off(int wm, int lane) {
    return (wm + (lane & 15)) * ASTR + (lane >> 4) * 4;
}
__device__ __forceinline__ int b_ldsm_off(int wn, int lane) {
    return (wn + ((lane >> 4) << 3) + (lane & 7)) * ASTR + ((lane >> 3) & 1) * 4;
}

// ---------------- 2-term fp16 GEMM (projections), block 128x64, double-buffered ----------------
__global__ __launch_bounds__(256, 2) void mma_gemm(
    const float* __restrict__ A, int lda, long long sAo, long long sAi,
    const float* __restrict__ B, int ldb, long long sBo, long long sBi,
    float* __restrict__ C, int ldc, long long sCo, long long sCi,
    int M, int N, int K, int inner,
    const float* __restrict__ bias, float alpha, const float* __restrict__ res)
{
    extern __shared__ unsigned smem_dyn[];

    int z = blockIdx.z;
    int zo = z / inner, zi = z - zo * inner;
    A += zo * sAo + zi * sAi;
    B += zo * sBo + zi * sBi;
    C += zo * sCo + zi * sCi;
    if (res) res += zo * sCo + zi * sCi;

    int tid = threadIdx.x, lane = tid & 31, warp = tid >> 5;
    int g = lane >> 2, tig = lane & 3;
    int wm = (warp & 3) * 32, wn = (warp >> 2) * 32;
    int m0 = blockIdx.y * 128, n0 = blockIdx.x * 64;

    int aoff = a_ldsm_off(wm, lane);
    int boff = b_ldsm_off(wn, lane);

    float c[2][4][4] = {};
    float4 aR[4];
    float4 bRt[2];

    int arA = tid >> 3, aqk = (tid & 7) << 2;
    int bn_ = tid >> 3, bqk = (tid & 7) << 2;

    #pragma unroll
    for (int i = 0; i < 4; i++) {
        int gm = m0 + arA + i*32;
        aR[i] = (gm < M) ? *(const float4*)&A[(long long)gm * lda + aqk] : make_float4(0,0,0,0);
    }
    bRt[0] = *(const float4*)&B[(long long)(n0 + bn_)      * ldb + bqk];
    bRt[1] = *(const float4*)&B[(long long)(n0 + bn_ + 32) * ldb + bqk];

    {
        unsigned* AsH = smem_dyn;          unsigned* AsL = smem_dyn + OFF_AL;
        unsigned* BsH = smem_dyn + OFF_BH;
        #pragma unroll
        for (int i = 0; i < 4; i++) {
            int base = (arA + i*32)*ASTR + (aqk >> 1);
            unsigned h2[2], l2[2];
            hsplit4(aR[i], h2, l2);
            *(uint2*)&AsH[base] = make_uint2(h2[0], h2[1]);
            *(uint2*)&AsL[base] = make_uint2(l2[0], l2[1]);
        }
        #pragma unroll
        for (int i = 0; i < 2; i++) {
            int base = (bn_ + i*32)*ASTR + (bqk >> 1);
            unsigned h2[2];
            hpack4(i ? bRt[1] : bRt[0], h2);
            *(uint2*)&BsH[base] = make_uint2(h2[0], h2[1]);
        }
    }
    __syncthreads();

    int sel = 0;
    for (int k0 = 0; k0 < K; k0 += 32) {
        unsigned* cb = smem_dyn + sel * BUFW;
        unsigned* nb = smem_dyn + (sel ^ 1) * BUFW;
        int k1 = k0 + 32;
        bool more = (k1 < K);

        if (more) {
            #pragma unroll
            for (int i = 0; i < 4; i++) {
                int gm = m0 + arA + i*32;
                aR[i] = (gm < M) ? *(const float4*)&A[(long long)gm * lda + k1 + aqk] : make_float4(0,0,0,0);
            }
            bRt[0] = *(const float4*)&B[(long long)(n0 + bn_)      * ldb + k1 + bqk];
            bRt[1] = *(const float4*)&B[(long long)(n0 + bn_ + 32) * ldb + k1 + bqk];
        }

        mma_step_ldsm(c, cb, aoff, boff, 0);
        mma_step_ldsm(c, cb, aoff, boff, 8);

        if (more) {
            unsigned* AsH = nb;          unsigned* AsL = nb + OFF_AL;
            unsigned* BsH = nb + OFF_BH;
            #pragma unroll
            for (int i = 0; i < 4; i++) {
                int base = (arA + i*32)*ASTR + (aqk >> 1);
                unsigned h2[2], l2[2];
                hsplit4(aR[i], h2, l2);
                *(uint2*)&AsH[base] = make_uint2(h2[0], h2[1]);
                *(uint2*)&AsL[base] = make_uint2(l2[0], l2[1]);
            }
            #pragma unroll
            for (int i = 0; i < 2; i++) {
                int base = (bn_ + i*32)*ASTR + (bqk >> 1);
                unsigned h2[2];
                hpack4(i ? bRt[1] : bRt[0], h2);
                *(uint2*)&BsH[base] = make_uint2(h2[0], h2[1]);
            }
        }
        __syncthreads();
        sel ^= 1;
    }

    #pragma unroll
    for (int mt = 0; mt < 2; mt++) {
        int r0 = m0 + wm + mt*16 + g;
        #pragma unroll
        for (int nt = 0; nt < 4; nt++) {
            int col = n0 + wn + nt*8 + tig*2;
            float bv0 = bias ? bias[col]   : 0.f;
            float bv1 = bias ? bias[col+1] : 0.f;
            if (r0 < M) {
                float v0 = alpha*c[mt][nt][0] + bv0;
                float v1 = alpha*c[mt][nt][1] + bv1;
                if (res) { v0 += res[(long long)r0*ldc + col]; v1 += res[(long long)r0*ldc + col + 1]; }
                C[(long long)r0*ldc + col]     = v0;
                C[(long long)r0*ldc + col + 1] = v1;
            }
            int r1 = r0 + 8;
            if (r1 < M) {
                float v2 = alpha*c[mt][nt][2] + bv0;
                float v3 = alpha*c[mt][nt][3] + bv1;
                if (res) { v2 += res[(long long)r1*ldc + col]; v3 += res[(long long)r1*ldc + col + 1]; }
                C[(long long)r1*ldc + col]     = v2;
                C[(long long)r1*ldc + col + 1] = v3;
            }
        }
    }
}

// ---------------- fused flash attention (fp16: Q split, K/V/P single; V via ldmatrix.trans) ----------------
#define FQH 0
#define FQL 4608
#define FKH 9216
#define FVH 11520
#define FA_SMEM (13824*4)

__global__ __launch_bounds__(256, 2) void fa_k(
    const float* __restrict__ Q, int ldq,
    const float* __restrict__ K, const float* __restrict__ V, int ldkv,
    float* __restrict__ O, int ldo, int kvlen)
{
    extern __shared__ unsigned smem_dyn[];
    unsigned* QsH = smem_dyn + FQH; unsigned* QsL = smem_dyn + FQL;
    unsigned* KsH = smem_dyn + FKH;
    unsigned* VsH = smem_dyn + FVH;   // [kv row 0..63][dh kpair 0..31] stride 36

    int tid = threadIdx.x, lane = tid & 31, warp = tid >> 5;
    int g = lane >> 2, tig = lane & 3;
    int b = blockIdx.y >> 4, h = blockIdx.y & 15;
    long long qrow0 = (long long)b * NQv + blockIdx.x * 128;
    Q += qrow0 * ldq + h * 64;
    O += qrow0 * ldo + h * 64;
    K += (long long)b * kvlen * ldkv + h * 64;
    V += (long long)b * kvlen * ldkv + h * 64;

    int aoffq = (warp*16 + (lane & 15)) * 36 + (lane >> 4) * 4;
    int boff  = (((lane >> 4) << 3) + (lane & 7)) * 36 + ((lane >> 3) & 1) * 4;
    // trans ldmatrix lane offset for V: rows = kv (lane&15), dh-half = (lane>>4)*8 halves
    int voff  = (lane & 15) * 36 + ((lane >> 4) & 1) * 4;

    float c_o[8][4] = {};
    float m0 = -3.4e38f, m1 = -3.4e38f, l0 = 0.f, l1 = 0.f;

    {
        int qrow = tid >> 1, qhalf = tid & 1;
        const float* qp = Q + (long long)qrow * ldq + qhalf * 32;
        int base = qrow * 36 + qhalf * 16;
        #pragma unroll
        for (int i = 0; i < 2; i++) {
            float4 v0 = *(const float4*)(qp + i*16);
            float4 v1 = *(const float4*)(qp + i*16 + 4);
            float4 v2 = *(const float4*)(qp + i*16 + 8);
            float4 v3 = *(const float4*)(qp + i*16 + 12);
            unsigned h4[4], l4[4];
            hsplit4(v0, h4, l4); hsplit4(v1, h4+2, l4+2);
            *(uint4*)&QsH[base + i*8] = *(uint4*)h4;
            *(uint4*)&QsL[base + i*8] = *(uint4*)l4;
            hsplit4(v2, h4, l4); hsplit4(v3, h4+2, l4+2);
            *(uint4*)&QsH[base + i*8 + 4] = *(uint4*)h4;
            *(uint4*)&QsL[base + i*8 + 4] = *(uint4*)l4;
        }
    }

    for (int kv0 = 0; kv0 < kvlen; kv0 += 64) {
        __syncthreads();
        // stage K tile (64 kv x 64 dh), row-major, hi only
        {
            int krow = tid >> 2, kq = tid & 3;
            const float* kp = K + (long long)(kv0 + krow) * ldkv + kq * 16;
            float4 v0 = *(const float4*)(kp);
            float4 v1 = *(const float4*)(kp + 4);
            float4 v2 = *(const float4*)(kp + 8);
            float4 v3 = *(const float4*)(kp + 12);
            int base = krow * 36 + kq * 8;
            unsigned h4[4];
            hpack4(v0, h4); hpack4(v1, h4+2);
            *(uint4*)&KsH[base] = *(uint4*)h4;
            hpack4(v2, h4); hpack4(v3, h4+2);
            *(uint4*)&KsH[base + 4] = *(uint4*)h4;
        }
        // stage V tile (64 kv x 64 dh), row-major like K (trans done by ldmatrix)
        {
            int krow = tid >> 2, kq = tid & 3;
            const float* vp = V + (long long)(kv0 + krow) * ldkv + kq * 16;
            float4 v0 = *(const float4*)(vp);
            float4 v1 = *(const float4*)(vp + 4);
            float4 v2 = *(const float4*)(vp + 8);
            float4 v3 = *(const float4*)(vp + 12);
            int base = krow * 36 + kq * 8;
            unsigned h4[4];
            hpack4(v0, h4); hpack4(v1, h4+2);
            *(uint4*)&VsH[base] = *(uint4*)h4;
            hpack4(v2, h4); hpack4(v3, h4+2);
            *(uint4*)&VsH[base + 4] = *(uint4*)h4;
        }
        __syncthreads();

        // S = Q K^T (2-term fp16)
        float c_s[8][4] = {};
        #pragma unroll
        for (int kp = 0; kp < 4; kp++) {
            unsigned qh[4], ql[4];
            ldsm4(QsH + aoffq + kp*8, qh);
            ldsm4(QsL + aoffq + kp*8, ql);
            #pragma unroll
            for (int gi = 0; gi < 4; gi++) {
                unsigned kh[4];
                ldsm4(KsH + boff + gi*576 + kp*8, kh);
                #pragma unroll
                for (int h2 = 0; h2 < 2; h2++) {
                    int nt = gi*2 + h2;
                    mma16(c_s[nt], qh, kh + h2*2);
                    mma16(c_s[nt], ql, kh + h2*2);
                }
            }
        }

        // online softmax (rows fully within warp)
        float t0 = -3.4e38f, t1 = -3.4e38f;
        #pragma unroll
        for (int nt = 0; nt < 8; nt++) {
            #pragma unroll
            for (int j = 0; j < 4; j++) c_s[nt][j] *= 0.125f;
            t0 = fmaxf(t0, fmaxf(c_s[nt][0], c_s[nt][1]));
            t1 = fmaxf(t1, fmaxf(c_s[nt][2], c_s[nt][3]));
        }
        t0 = fmaxf(t0, __shfl_xor_sync(0xffffffffu, t0, 1));
        t0 = fmaxf(t0, __shfl_xor_sync(0xffffffffu, t0, 2));
        t1 = fmaxf(t1, __shfl_xor_sync(0xffffffffu, t1, 1));
        t1 = fmaxf(t1, __shfl_xor_sync(0xffffffffu, t1, 2));
        float mn0 = fmaxf(m0, t0), mn1 = fmaxf(m1, t1);
        float es0 = __expf(m0 - mn0), es1 = __expf(m1 - mn1);
        float s0 = 0.f, s1 = 0.f;
        #pragma unroll
        for (int nt = 0; nt < 8; nt++) {
            c_s[nt][0] = __expf(c_s[nt][0] - mn0); s0 += c_s[nt][0];
            c_s[nt][1] = __expf(c_s[nt][1] - mn0); s0 += c_s[nt][1];
            c_s[nt][2] = __expf(c_s[nt][2] - mn1); s1 += c_s[nt][2];
            c_s[nt][3] = __expf(c_s[nt][3] - mn1); s1 += c_s[nt][3];
        }
        s0 += __shfl_xor_sync(0xffffffffu, s0, 1);
        s0 += __shfl_xor_sync(0xffffffffu, s0, 2);
        s1 += __shfl_xor_sync(0xffffffffu, s1, 1);
        s1 += __shfl_xor_sync(0xffffffffu, s1, 2);
        l0 = l0 * es0 + s0;  l1 = l1 * es1 + s1;
        m0 = mn0; m1 = mn1;
        #pragma unroll
        for (int nt = 0; nt < 8; nt++) {
            c_o[nt][0] *= es0; c_o[nt][1] *= es0;
            c_o[nt][2] *= es1; c_o[nt][3] *= es1;
        }

        // O += P V  (P single fp16 from registers; V via trans ldmatrix)
        #pragma unroll
        for (int kk = 0; kk < 4; kk++) {
            unsigned pa[4];
            pa[0] = hpack2(c_s[2*kk][0],   c_s[2*kk][1]);
            pa[1] = hpack2(c_s[2*kk][2],   c_s[2*kk][3]);
            pa[2] = hpack2(c_s[2*kk+1][0], c_s[2*kk+1][1]);
            pa[3] = hpack2(c_s[2*kk+1][2], c_s[2*kk+1][3]);
            #pragma unroll
            for (int gi = 0; gi < 4; gi++) {
                unsigned vb[4];
                ldsm4t(VsH + kk*576 + gi*8 + voff, vb);
                #pragma unroll
                for (int h2 = 0; h2 < 2; h2++) {
                    int nt = gi*2 + h2;
                    mma16(c_o[nt], pa, vb + h2*2);
                }
            }
        }
    }

    float inv0 = 1.0f / l0, inv1 = 1.0f / l1;
    int r0 = warp*16 + g, r1 = r0 + 8;
    #pragma unroll
    for (int nt = 0; nt < 8; nt++) {
        int col = nt*8 + tig*2;
        O[(long long)r0*ldo + col]     = c_o[nt][0]*inv0;
        O[(long long)r0*ldo + col + 1] = c_o[nt][1]*inv0;
        O[(long long)r1*ldo + col]     = c_o[nt][2]*inv1;
        O[(long long)r1*ldo + col + 1] = c_o[nt][3]*inv1;
    }
}

// ---------------- JAX threefry2x32 / normal ----------------
__device__ __forceinline__ void threefry42(unsigned c0, unsigned c1, unsigned& o0, unsigned& o1) {
    const unsigned k0 = 0u, k1 = 42u;
    const unsigned k2 = 0x1BD11BDAu ^ k0 ^ k1;
    unsigned x0 = c0 + k0, x1 = c1 + k1;
#define TF_R(r) { x0 += x1; x1 = (x1 << r) | (x1 >> (32 - r)); x1 ^= x0; }
    TF_R(13) TF_R(15) TF_R(26) TF_R(6)   x0 += k1; x1 += k2 + 1u;
    TF_R(17) TF_R(29) TF_R(16) TF_R(24)  x0 += k2; x1 += k0 + 2u;
    TF_R(13) TF_R(15) TF_R(26) TF_R(6)   x0 += k0; x1 += k1 + 3u;
    TF_R(17) TF_R(29) TF_R(16) TF_R(24)  x0 += k1; x1 += k2 + 4u;
    TF_R(13) TF_R(15) TF_R(26) TF_R(6)   x0 += k2; x1 += k0 + 5u;
#undef TF_R
    o0 = x0; o1 = x1;
}

__device__ __forceinline__ float erfinv_f(float x) {
    float w = -log1pf(__fmul_rn(-x, x));
    float p;
    if (w < 5.0f) {
        w = __fadd_rn(w, -2.5f);
        p = 2.81022636e-08f;
        p = __fadd_rn(__fmul_rn(p, w),  3.43273939e-07f);
        p = __fadd_rn(__fmul_rn(p, w), -3.5233877e-06f);
        p = __fadd_rn(__fmul_rn(p, w), -4.39150654e-06f);
        p = __fadd_rn(__fmul_rn(p, w),  0.00021858087f);
        p = __fadd_rn(__fmul_rn(p, w), -0.00125372503f);
        p = __fadd_rn(__fmul_rn(p, w), -0.00417768164f);
        p = __fadd_rn(__fmul_rn(p, w),  0.246640727f);
        p = __fadd_rn(__fmul_rn(p, w),  1.50140941f);
    } else {
        w = __fadd_rn(sqrtf(w), -3.0f);
        p = -0.000200214257f;
        p = __fadd_rn(__fmul_rn(p, w),  0.000100950558f);
        p = __fadd_rn(__fmul_rn(p, w),  0.00134934322f);
        p = __fadd_rn(__fmul_rn(p, w), -0.00367342844f);
        p = __fadd_rn(__fmul_rn(p, w),  0.00573950773f);
        p = __fadd_rn(__fmul_rn(p, w), -0.0076224613f);
        p = __fadd_rn(__fmul_rn(p, w),  0.00943887047f);
        p = __fadd_rn(__fmul_rn(p, w),  1.00167406f);
        p = __fadd_rn(__fmul_rn(p, w),  2.83297682f);
    }
    return __fmul_rn(p, x);
}

__device__ __forceinline__ float jax_normal(int i) {
    unsigned o0, o1;
    threefry42(0u, (unsigned)i, o0, o1);
    unsigned bits = o0 ^ o1;
    unsigned fb = (bits >> 9) | 0x3f800000u;
    float u01 = __fadd_rn(__uint_as_float(fb), -1.0f);
    const float lo = -0.99999994f;
    float u = __fadd_rn(__fmul_rn(u01, 2.0f), lo);
    u = fmaxf(lo, u);
    return __fmul_rn(1.41421354f, erfinv_f(u));
}

// ---------------- MoE router ----------------
__global__ void zero_counts_k() { if (threadIdx.x < Ev) g_counts[threadIdx.x] = 0; }

__global__ void router_k(const float* __restrict__ xm,
                         const float* __restrict__ rw, const float* __restrict__ rb,
                         const float* __restrict__ nw, const float* __restrict__ nb) {
    int t = blockIdx.x;
    int tid = threadIdx.x;
    int w = tid >> 5, lane = tid & 31;
    __shared__ float sl[8], sn[8];
    const float* xr = xm + (long long)t * 1024;
    const float* rwe = rw + w * 1024;
    const float* nwe = nw + w * 1024;
    float sr = 0.f, s_n = 0.f;
    for (int d = lane; d < 1024; d += 32) {
        float xv = xr[d];
        sr  += xv * rwe[d];
        s_n += xv * nwe[d];
    }
    #pragma unroll
    for (int o = 16; o; o >>= 1) {
        sr  += __shfl_down_sync(0xffffffffu, sr, o);
        s_n += __shfl_down_sync(0xffffffffu, s_n, o);
    }
    if (lane == 0) { sl[w] = sr + rb[w]; sn[w] = s_n + nb[w]; }
    __syncthreads();
    if (tid == 0) {
        float noisy[8];
        #pragma unroll
        for (int e = 0; e < 8; e++) {
            float nrm = jax_normal(t * 8 + e);
            float zz = sn[e];
            float sp = fmaxf(zz, 0.f) + log1pf(expf(-fabsf(zz)));
            noisy[e] = sl[e] + nrm * sp;
        }
        int i1 = 0;
        #pragma unroll
        for (int e = 1; e < 8; e++) if (noisy[e] > noisy[i1]) i1 = e;
        int i2 = (i1 == 0) ? 1 : 0;
        #pragma unroll
        for (int e = 0; e < 8; e++) if (e != i1 && noisy[e] > noisy[i2]) i2 = e;
        float mx = noisy[i1];
        float e1 = expf(noisy[i1] - mx);
        float e2 = expf(noisy[i2] - mx);
        float Z  = e1 + e2;
        g_probs[2*t]   = e1 / Z;
        g_probs[2*t+1] = e2 / Z;
        int p1 = atomicAdd(&g_counts[i1], 1); g_elist[i1 * MAXTOK + p1] = 2*t;
        int p2 = atomicAdd(&g_counts[i2], 1); g_elist[i2 * MAXTOK + p2] = 2*t + 1;
    }
}

// ---------------- MoE 1-term fp16 GEMMs (round-13 coalesced staging) ----------------
// GEMM1: h = gelu(xm @ w1 + b1), output fp16 to g_hh
__global__ __launch_bounds__(256, 2) void moe_mma1(const float* __restrict__ xm,
                                                   const float* __restrict__ w1,
                                                   const float* __restrict__ b1) {
    extern __shared__ unsigned smem_dyn[];
    __shared__ int slots[128];

    int e = blockIdx.z;
    int cnt = g_counts[e];
    int m0 = blockIdx.y * 128;
    if (m0 >= cnt) return;
    int n0 = blockIdx.x * 64;

    int tid = threadIdx.x, lane = tid & 31, warp = tid >> 5;
    int g = lane >> 2, tig = lane & 3;
    int wm = (warp & 3) * 32, wn = (warp >> 2) * 32;
    if (tid < 128) slots[tid] = (m0 + tid < cnt) ? g_elist[e * MAXTOK + m0 + tid] : -1;
    __syncthreads();

    int aoff = a_ldsm_off(wm, lane);
    int boff = b_ldsm_off(wn, lane);

    const float* Be = w1 + (long long)e * 1024 * 4096;
    float c[2][4][4] = {};
    float4 aR[4];
    float  bf[8];

    int arA = tid >> 3, aqk = (tid & 7) << 2;
    int bnc = tid & 63, bkg = tid >> 6;
    int sg[4];
    #pragma unroll
    for (int i = 0; i < 4; i++) sg[i] = slots[arA + i*32];

    #pragma unroll
    for (int i = 0; i < 4; i++)
        aR[i] = (sg[i] >= 0) ? *(const float4*)&xm[(long long)(sg[i] >> 1)*1024 + aqk] : make_float4(0,0,0,0);
    #pragma unroll
    for (int j = 0; j < 8; j++)
        bf[j] = Be[(long long)(bkg*8 + j) * 4096 + n0 + bnc];

    {
        unsigned* AsH = smem_dyn;  unsigned* BsH = smem_dyn + MOFF_BH;
        #pragma unroll
        for (int i = 0; i < 4; i++) {
            int base = (arA + i*32)*ASTR + (aqk >> 1);
            unsigned h2[2];
            hpack4(aR[i], h2);
            *(uint2*)&AsH[base] = make_uint2(h2[0], h2[1]);
        }
        unsigned h4[4];
        h4[0] = hpack2(bf[0], bf[1]); h4[1] = hpack2(bf[2], bf[3]);
        h4[2] = hpack2(bf[4], bf[5]); h4[3] = hpack2(bf[6], bf[7]);
        *(uint4*)&BsH[bnc*ASTR + bkg*4] = *(uint4*)h4;
    }
    __syncthreads();

    int sel = 0;
    for (int k0 = 0; k0 < 1024; k0 += 32) {
        unsigned* cb = smem_dyn + sel * MBUFW;
        unsigned* nb = smem_dyn + (sel ^ 1) * MBUFW;
        int k1 = k0 + 32;
        bool more = (k1 < 1024);
        if (more) {
            #pragma unroll
            for (int i = 0; i < 4; i++)
                aR[i] = (sg[i] >= 0) ? *(const float4*)&xm[(long long)(sg[i] >> 1)*1024 + k1 + aqk] : make_float4(0,0,0,0);
            #pragma unroll
            for (int j = 0; j < 8; j++)
                bf[j] = Be[(long long)(k1 + bkg*8 + j) * 4096 + n0 + bnc];
        }
        mma_step_1t(c, cb, aoff, boff, 0);
        mma_step_1t(c, cb, aoff, boff, 8);
        if (more) {
            unsigned* AsH = nb;  unsigned* BsH = nb + MOFF_BH;
            #pragma unroll
            for (int i = 0; i < 4; i++) {
                int base = (arA + i*32)*ASTR + (aqk >> 1);
                unsigned h2[2];
                hpack4(aR[i], h2);
                *(uint2*)&AsH[base] = make_uint2(h2[0], h2[1]);
            }
            unsigned h4[4];
            h4[0] = hpack2(bf[0], bf[1]); h4[1] = hpack2(bf[2], bf[3]);
            h4[2] = hpack2(bf[4], bf[5]); h4[3] = hpack2(bf[6], bf[7]);
            *(uint4*)&BsH[bnc*ASTR + bkg*4] = *(uint4*)h4;
        }
        __syncthreads();
        sel ^= 1;
    }

    #pragma unroll
    for (int mt = 0; mt < 2; mt++) {
        int lr0 = wm + mt*16 + g;
        int s0 = slots[lr0], s1 = slots[lr0 + 8];
        #pragma unroll
        for (int nt = 0; nt < 4; nt++) {
            int col = n0 + wn + nt*8 + tig*2;
            float bv0 = b1[e*4096 + col], bv1 = b1[e*4096 + col + 1];
            if (s0 >= 0) {
                float v0 = c[mt][nt][0] + bv0;
                float v1 = c[mt][nt][1] + bv1;
                v0 = 0.5f * v0 * (1.0f + erff(v0 * 0.70710677f));
                v1 = 0.5f * v1 * (1.0f + erff(v1 * 0.70710677f));
                *(__half2*)&g_hh[(long long)s0*4096 + col] = __floats2half2_rn(v0, v1);
            }
            if (s1 >= 0) {
                float v2 = c[mt][nt][2] + bv0;
                float v3 = c[mt][nt][3] + bv1;
                v2 = 0.5f * v2 * (1.0f + erff(v2 * 0.70710677f));
                v3 = 0.5f * v3 * (1.0f + erff(v3 * 0.70710677f));
                *(__half2*)&g_hh[(long long)s1*4096 + col] = __floats2half2_rn(v2, v3);
            }
        }
    }
}

// GEMM2: eo = h @ w2 + b2  (h fp16 in g_hh: raw uint2 staging, zero conversion)
__global__ __launch_bounds__(256, 2) void moe_mma2(const float* __restrict__ w2,
                                                   const float* __restrict__ b2) {
    extern __shared__ unsigned smem_dyn[];
    __shared__ int slots[128];

    int e = blockIdx.z;
    int cnt = g_counts[e];
    int m0 = blockIdx.y * 128;
    if (m0 >= cnt) return;
    int n0 = blockIdx.x * 64;

    int tid = threadIdx.x, lane = tid & 31, warp = tid >> 5;
    int g = lane >> 2, tig = lane & 3;
    int wm = (warp & 3) * 32, wn = (warp >> 2) * 32;
    if (tid < 128) slots[tid] = (m0 + tid < cnt) ? g_elist[e * MAXTOK + m0 + tid] : -1;
    __syncthreads();

    int aoff = a_ldsm_off(wm, lane);
    int boff = b_ldsm_off(wn, lane);

    const float* Be = w2 + (long long)e * 4096 * 1024;
    float c[2][4][4] = {};
    uint2 aU[4];
    float bf[8];

    int arA = tid >> 3, aqk = (tid & 7) << 2;   // 4 halves per row-chunk (8B)
    int bnc = tid & 63, bkg = tid >> 6;
    int sg[4];
    #pragma unroll
    for (int i = 0; i < 4; i++) sg[i] = slots[arA + i*32];
    const uint2 Z2 = make_uint2(0,0);

    #pragma unroll
    for (int i = 0; i < 4; i++)
        aU[i] = (sg[i] >= 0) ? *(const uint2*)&g_hh[(long long)sg[i]*4096 + aqk] : Z2;
    #pragma unroll
    for (int j = 0; j < 8; j++)
        bf[j] = Be[(long long)(bkg*8 + j) * 1024 + n0 + bnc];

    {
        unsigned* AsH = smem_dyn;  unsigned* BsH = smem_dyn + MOFF_BH;
        #pragma unroll
        for (int i = 0; i < 4; i++) {
            int base = (arA + i*32)*ASTR + (aqk >> 1);
            *(uint2*)&AsH[base] = aU[i];
        }
        unsigned h4[4];
        h4[0] = hpack2(bf[0], bf[1]); h4[1] = hpack2(bf[2], bf[3]);
        h4[2] = hpack2(bf[4], bf[5]); h4[3] = hpack2(bf[6], bf[7]);
        *(uint4*)&BsH[bnc*ASTR + bkg*4] = *(uint4*)h4;
    }
    __syncthreads();

    int sel = 0;
    for (int k0 = 0; k0 < 4096; k0 += 32) {
        unsigned* cb = smem_dyn + sel * MBUFW;
        unsigned* nb = smem_dyn + (sel ^ 1) * MBUFW;
        int k1 = k0 + 32;
        bool more = (k1 < 4096);
        if (more) {
            #pragma unroll
            for (int i = 0; i < 4; i++)
                aU[i] = (sg[i] >= 0) ? *(const uint2*)&g_hh[(long long)sg[i]*4096 + k1 + aqk] : Z2;
            #pragma unroll
            for (int j = 0; j < 8; j++)
                bf[j] = Be[(long long)(k1 + bkg*8 + j) * 1024 + n0 + bnc];
        }
        mma_step_1t(c, cb, aoff, boff, 0);
        mma_step_1t(c, cb, aoff, boff, 8);
        if (more) {
            unsigned* AsH = nb;  unsigned* BsH = nb + MOFF_BH;
            #pragma unroll
            for (int i = 0; i < 4; i++) {
                int base = (arA + i*32)*ASTR + (aqk >> 1);
                *(uint2*)&AsH[base] = aU[i];
            }
            unsigned h4[4];
            h4[0] = hpack2(bf[0], bf[1]); h4[1] = hpack2(bf[2], bf[3]);
            h4[2] = hpack2(bf[4], bf[5]); h4[3] = hpack2(bf[6], bf[7]);
            *(uint4*)&BsH[bnc*ASTR + bkg*4] = *(uint4*)h4;
        }
        __syncthreads();
        sel ^= 1;
    }

    #pragma unroll
    for (int mt = 0; mt < 2; mt++) {
        int lr0 = wm + mt*16 + g;
        int s0 = slots[lr0], s1 = slots[lr0 + 8];
        #pragma unroll
        for (int nt = 0; nt < 4; nt++) {
            int col = n0 + wn + nt*8 + tig*2;
            float bv0 = b2[e*1024 + col], bv1 = b2[e*1024 + col + 1];
            if (s0 >= 0) {
                g_eo[(long long)s0*1024 + col]     = c[mt][nt][0] + bv0;
                g_eo[(long long)s0*1024 + col + 1] = c[mt][nt][1] + bv1;
            }
            if (s1 >= 0) {
                g_eo[(long long)s1*1024 + col]     = c[mt][nt][2] + bv0;
                g_eo[(long long)s1*1024 + col + 1] = c[mt][nt][3] + bv1;
            }
        }
    }
}

__global__ void combine_k(const float* __restrict__ x, float* __restrict__ out) {
    int idx = blockIdx.x * 256 + threadIdx.x;
    int t = idx >> 10, d = idx & 1023;
    float v = x[idx];
    v += g_probs[2*t]     * g_eo[(long long)(2*t)     * 1024 + d];
    v += g_probs[2*t + 1] * g_eo[(long long)(2*t + 1) * 1024 + d];
    out[idx] = v;
}

// ---------------- launcher ----------------
extern "C" void kernel_launch(void* const* d_in, const int* in_sizes, int n_in,
                              void* d_out, int out_size) {
    const float* q        = (const float*)d_in[0];
    const float* kv       = (const float*)d_in[1];
    const float* ln_cq_g  = (const float*)d_in[2];
    const float* ln_cq_b  = (const float*)d_in[3];
    const float* ln_ckv_g = (const float*)d_in[4];
    const float* ln_ckv_b = (const float*)d_in[5];
    const float* ln_s_g   = (const float*)d_in[6];
    const float* ln_s_b   = (const float*)d_in[7];
    const float* ln_m_g   = (const float*)d_in[8];
    const float* ln_m_b   = (const float*)d_in[9];
    const float* ca_in_w  = (const float*)d_in[10];
    const float* ca_in_b  = (const float*)d_in[11];
    const float* ca_out_w = (const float*)d_in[12];
    const float* ca_out_b = (const float*)d_in[13];
    const float* sa_in_w  = (const float*)d_in[14];
    const float* sa_in_b  = (const float*)d_in[15];
    const float* sa_out_w = (const float*)d_in[16];
    const float* sa_out_b = (const float*)d_in[17];
    const float* moe_rw   = (const float*)d_in[18];
    const float* moe_rb   = (const float*)d_in[19];
    const float* moe_nw   = (const float*)d_in[20];
    const float* moe_nb   = (const float*)d_in[21];
    const float* moe_w1   = (const float*)d_in[22];
    const float* moe_b1   = (const float*)d_in[23];
    const float* moe_w2   = (const float*)d_in[24];
    const float* moe_b2   = (const float*)d_in[25];
    float* out = (float*)d_out;

    float *p_x, *p_ln1, *p_lnkv, *p_qp, *p_kvp, *p_ao;
    cudaGetSymbolAddress((void**)&p_x,    g_x);
    cudaGetSymbolAddress((void**)&p_ln1,  g_ln1);
    cudaGetSymbolAddress((void**)&p_lnkv, g_lnkv);
    cudaGetSymbolAddress((void**)&p_qp,   g_qp);
    cudaGetSymbolAddress((void**)&p_kvp,  g_kvp);
    cudaGetSymbolAddress((void**)&p_ao,   g_ao);

    cudaFuncSetAttribute(mma_gemm, cudaFuncAttributeMaxDynamicSharedMemorySize, DSMEM_BYTES);
    cudaFuncSetAttribute(moe_mma1, cudaFuncAttributeMaxDynamicSharedMemorySize, MDSMEM_BYTES);
    cudaFuncSetAttribute(moe_mma2, cudaFuncAttributeMaxDynamicSharedMemorySize, MDSMEM_BYTES);
    cudaFuncSetAttribute(fa_k,     cudaFuncAttributeMaxDynamicSharedMemorySize, FA_SMEM);

    const long long ZL = 0;

    // ===== Cross-attention =====
    ln_k<<<TQ, 256>>>(q,  p_ln1,  ln_cq_g,  ln_cq_b);
    ln_k<<<TKV, 256>>>(kv, p_lnkv, ln_ckv_g, ln_ckv_b);

    mma_gemm<<<dim3(16, 16, 1), 256, DSMEM_BYTES>>>(p_ln1, 1024, ZL, ZL,
        ca_in_w, 1024, ZL, ZL, p_qp, 1024, ZL, ZL,
        TQ, 1024, 1024, 1, ca_in_b, 1.0f, nullptr);
    mma_gemm<<<dim3(32, 32, 1), 256, DSMEM_BYTES>>>(p_lnkv, 1024, ZL, ZL,
        ca_in_w + 1024*1024, 1024, ZL, ZL, p_kvp, 2048, ZL, ZL,
        TKV, 2048, 1024, 1, ca_in_b + 1024, 1.0f, nullptr);

    fa_k<<<dim3(8, 32), 256, FA_SMEM>>>(p_qp, 1024, p_kvp, p_kvp + 1024, 2048,
                                        p_ao, 1024, NKVv);

    mma_gemm<<<dim3(16, 16, 1), 256, DSMEM_BYTES>>>(p_ao, 1024, ZL, ZL,
        ca_out_w, 1024, ZL, ZL, p_x, 1024, ZL, ZL,
        TQ, 1024, 1024, 1, ca_out_b, 1.0f, q);

    // ===== Self-attention =====
    ln_k<<<TQ, 256>>>(p_x, p_ln1, ln_s_g, ln_s_b);
    mma_gemm<<<dim3(48, 16, 1), 256, DSMEM_BYTES>>>(p_ln1, 1024, ZL, ZL,
        sa_in_w, 1024, ZL, ZL, p_kvp, 3072, ZL, ZL,
        TQ, 3072, 1024, 1, sa_in_b, 1.0f, nullptr);

    fa_k<<<dim3(8, 32), 256, FA_SMEM>>>(p_kvp, 3072, p_kvp + 1024, p_kvp + 2048, 3072,
                                        p_ao, 1024, NQv);

    mma_gemm<<<dim3(16, 16, 1), 256, DSMEM_BYTES>>>(p_ao, 1024, ZL, ZL,
        sa_out_w, 1024, ZL, ZL, p_x, 1024, ZL, ZL,
        TQ, 1024, 1024, 1, sa_out_b, 1.0f, p_x);

    // ===== MoE =====
    ln_k<<<TQ, 256>>>(p_x, p_ln1, ln_m_g, ln_m_b);
    zero_counts_k<<<1, 32>>>();
    router_k<<<TQ, 256>>>(p_ln1, moe_rw, moe_rb, moe_nw, moe_nb);
    moe_mma1<<<dim3(64, 16, 8), 256, MDSMEM_BYTES>>>(p_ln1, moe_w1, moe_b1);
    moe_mma2<<<dim3(16, 16, 8), 256, MDSMEM_BYTES>>>(moe_w2, moe_b2);
    combine_k<<<(TQ*Dv)/256, 256>>>(p_x, out);
}